// round 13
// baseline (speedup 1.0000x reference)
#include <cuda_runtime.h>
#include <cuda_bf16.h>
#include <cstdint>

#define NPROMPT 20
#define RPB 8          // rows per copy block
#define DVC 192        // float4s per row (D=768)

// Prep outputs:
__device__ int g_patch[4096 * NPROMPT];          // (b,r) -> local l or -1
__device__ long long g_sid[4096];                // resolved sample id per b
__device__ unsigned char g_skip8[(1 << 16) / 8]; // 1 take-bit per row, 8 rows/byte
__device__ int g_ready[4096];                    // prep-done flag per batch row
// Fallback-path scratch.
__device__ unsigned long long g_src[1 << 16];

// ===========================================================================
// Single fused kernel. Blocks [0, B): prep. Blocks [B, B+BL/RPB): copy.
// Requires L % RPB == 0, Dv == DVC, B <= 256, L <= 4096.
// ===========================================================================
__global__ void __launch_bounds__(256) fused_all_kernel(
    const int* __restrict__ mask,
    const float4* __restrict__ in,
    const float4* __restrict__ prompts,
    const void* __restrict__ sid_raw,
    float4* __restrict__ out,
    float* __restrict__ mask_out,
    int B, int L, long long NS) {
    int t = threadIdx.x;

    if ((int)blockIdx.x < B) {
        // ================= PREP role =================
        int b = blockIdx.x;
        int lane = t & 31, warp = t >> 5;
        __shared__ int wtot[8];
        __shared__ int carry;
        __shared__ int s_all0;
        if (t == 0) { carry = 0; s_all0 = 1; }
        __syncthreads();

        // parallel sid dtype probe: int64 iff all odd 32-bit words of the
        // first B words are zero (ids < 2^31). In-bounds for both layouts.
        const int* sw = (const int*)sid_raw;
        if (t < B && (t & 1) && sw[t] != 0) s_all0 = 0;  // benign write-0 race
        __syncthreads();
        long long s = s_all0 ? ((const long long*)sid_raw)[b]
                             : (long long)sw[b];
        if (s < 0) s = 0;
        if (s >= NS) s = NS - 1;
        if (t == 0) g_sid[b] = s;
        if (t < NPROMPT) g_patch[b * NPROMPT + t] = -1;

        for (int c0 = 0; c0 < L; c0 += 256) {
            int l = c0 + t;
            int m = 0, pad = 0;
            if (l < L) {
                m = mask[(size_t)b * L + l];
                pad = (m == 0);
            }
            unsigned bal = __ballot_sync(0xFFFFFFFFu, pad);
            if (lane == 0) wtot[warp] = __popc(bal);
            __syncthreads();
            int prefix = carry;
            for (int w = 0; w < warp; ++w) prefix += wtot[w];
            int rank = prefix + __popc(bal & ((1u << lane) - 1u));

            int take = (l < L) && pad && (rank < NPROMPT);
            if (take) g_patch[b * NPROMPT + rank] = l;
            if (l < L && mask_out)
                mask_out[(size_t)b * L + l] = take ? 1.0f : (float)m;

            unsigned tb = __ballot_sync(0xFFFFFFFFu, take);
            if ((lane & 7) == 0 && l < L)
                g_skip8[((size_t)b * L + l) >> 3] =
                    (unsigned char)((tb >> lane) & 0xFFu);

            __syncthreads();
            if (t == 0) {
                int tot = 0;
                for (int w = 0; w < 8; ++w) tot += wtot[w];
                carry += tot;
            }
            __syncthreads();
        }
        __threadfence();
        __syncthreads();
        if (t == 0) *(volatile int*)&g_ready[b] = 1;
        return;
    }

    // ================= COPY role: RPB rows, 6 float4 per thread =================
    int cb = blockIdx.x - B;
    size_t base = (size_t)cb * (RPB * DVC);     // RPB*DVC = 1536 = 6*256

    // speculative front-batched input loads (independent of prep)
    float4 v[6];
    #pragma unroll
    for (int k = 0; k < 6; ++k) v[k] = in[base + t + k * 256];

    int b = cb / (L / RPB);
    // wait for prep of this batch row (instant on graph replays)
    if (*(volatile int*)&g_ready[b] == 0) {
        while (*(volatile int*)&g_ready[b] == 0) { __nanosleep(64); }
    }
    __threadfence();

    unsigned flags = g_skip8[cb];
    if (flags == 0) {
        #pragma unroll
        for (int k = 0; k < 6; ++k) out[base + t + k * 256] = v[k];
        return;
    }

    // mixed block: store non-patched rows from input
    #pragma unroll
    for (int k = 0; k < 6; ++k) {
        int r = (t + k * 256) / DVC;
        if (!((flags >> r) & 1u)) out[base + t + k * 256] = v[k];
    }
    // patched rows: copy prompt data
    long long s = g_sid[b];
    int l0 = cb * RPB - b * L;                   // local l of row 0 in block
    for (int r = 0; r < RPB; ++r) {
        if (!((flags >> r) & 1u)) continue;
        int l = l0 + r;
        int rr = 0;
        for (int i = 0; i < NPROMPT; ++i)
            if (g_patch[b * NPROMPT + i] == l) { rr = i; break; }
        const float4* src = prompts + ((size_t)s * NPROMPT + rr) * DVC;
        float4* dst = out + base + (size_t)r * DVC;
        if (t < DVC) dst[t] = src[t];
    }
}

// ===========================================================================
// Fallback path (unexpected shapes): resolved-pointer prep + per-row copy.
// ===========================================================================
__global__ void prep_serial_kernel(const int* __restrict__ mask,
                                   const float* __restrict__ in,
                                   const float* __restrict__ prompts,
                                   const void* __restrict__ sid_raw,
                                   float* __restrict__ mask_out,
                                   int B, int L, int D, long long NS) {
    int b = blockIdx.x * blockDim.x + threadIdx.x;
    if (b >= B) return;
    const int* sw = (const int*)sid_raw;
    int all0 = 1;
    for (int i = 1; i < B; i += 2)
        if (sw[i] != 0) { all0 = 0; break; }
    long long s = all0 ? ((const long long*)sid_raw)[b] : (long long)sw[b];
    if (s < 0) s = 0;
    if (s >= NS) s = NS - 1;
    int cnt = 0;
    for (int l = 0; l < L; ++l) {
        size_t row = (size_t)b * L + l;
        int m = mask[row];
        int pad = (m == 0);
        int take = pad && (cnt < NPROMPT);
        const float* src = take
            ? prompts + ((size_t)s * NPROMPT + cnt) * (size_t)D
            : in + row * (size_t)D;
        g_src[row] = (unsigned long long)src;
        if (mask_out) mask_out[row] = take ? 1.0f : (float)m;
        cnt += pad;
    }
}

__global__ void copy_scalar_kernel(float* __restrict__ out, int BL, int D) {
    int row = blockIdx.x;
    if (row >= BL) return;
    const float* __restrict__ src = (const float*)g_src[row];
    float* __restrict__ dst = out + (size_t)row * D;
    for (int c = threadIdx.x; c < D; c += blockDim.x) dst[c] = src[c];
}

// ===========================================================================
extern "C" void kernel_launch(void* const* d_in, const int* in_sizes, int n_in,
                              void* d_out, int out_size) {
    // Bind inputs by size rank:
    //   smallest     -> sample_id_tensor [B]
    //   2nd smallest -> attention_mask   [B*L]
    //   2nd largest  -> input_embeds     [B*L*D]
    //   largest      -> prompt_embeddings [NS*NPROMPT*D]
    int idx[4] = {0, 1, 2, 3};
    for (int i = 0; i < 4; ++i)
        for (int j = i + 1; j < 4; ++j)
            if (in_sizes[idx[j]] < in_sizes[idx[i]]) {
                int t = idx[i]; idx[i] = idx[j]; idx[j] = t;
            }
    const void*  sid     = d_in[idx[0]];
    const int*   mask    = (const int*)d_in[idx[1]];
    const float* embeds  = (const float*)d_in[idx[2]];
    const float* prompts = (const float*)d_in[idx[3]];

    int B  = in_sizes[idx[0]];
    int BL = in_sizes[idx[1]];
    int L  = BL / B;
    long long D  = (long long)in_sizes[idx[2]] / BL;
    long long NS = (long long)in_sizes[idx[3]] / (NPROMPT * D);

    float* out = (float*)d_out;
    size_t embed_elems = (size_t)BL * (size_t)D;
    float* mask_out = ((size_t)out_size >= embed_elems + (size_t)BL)
                          ? out + embed_elems
                          : nullptr;

    bool ok = (D == 4 * DVC) && (L % RPB) == 0 && L <= 4096 &&
              B <= 256 && BL <= (1 << 16);

    if (ok) {
        int blocks = B + BL / RPB;
        fused_all_kernel<<<blocks, 256>>>(
            mask, (const float4*)embeds, (const float4*)prompts, sid,
            (float4*)out, mask_out, B, L, NS);
    } else {
        int threads = 128;
        int blocks = (B + threads - 1) / threads;
        prep_serial_kernel<<<blocks, threads>>>(mask, embeds, prompts, sid,
                                                mask_out, B, (int)L, (int)D, NS);
        int cthreads = (int)(D < 1024 ? ((D + 31) / 32) * 32 : 1024);
        copy_scalar_kernel<<<BL, cthreads>>>(out, BL, (int)D);
    }
}

// round 17
// speedup vs baseline: 1.9698x; 1.9698x over previous
#include <cuda_runtime.h>
#include <cuda_bf16.h>
#include <cstdint>

#define NPROMPT 20
#define RPB 8          // rows per copy block
#define DVC 192        // float4s per row (D=768)

// Prep outputs:
__device__ int g_patch[4096 * NPROMPT];          // (b,r) -> local l or -1
__device__ long long g_sid[4096];                // resolved sample id per b
__device__ unsigned char g_skip8[(1 << 16) / 8]; // take-bit per row, 8 rows/byte
// Fallback-path scratch.
__device__ unsigned long long g_src[1 << 16];

// ===========================================================================
// K1 prep: one block per batch row, L threads (L <= 1024, L % 8 == 0).
// Minimal R5-style: probe + ballot scan + mask_out + patch table + flag bytes.
// ===========================================================================
__global__ void prep_kernel(const int* __restrict__ mask,
                            const void* __restrict__ sid_raw,
                            float* __restrict__ mask_out,
                            int B, int L, long long NS) {
    int b = blockIdx.x;
    int t = threadIdx.x;
    int lane = t & 31;
    int warp = t >> 5;

    // sid dtype probe: int64 iff all odd 32-bit words among the first B words
    // are zero (ids < 2^31). B words ~= 1 cache line -> cheap serial loop.
    const int* sw = (const int*)sid_raw;
    int all0 = 1;
    for (int i = 1; i < B; i += 2)
        if (sw[i] != 0) { all0 = 0; break; }
    long long s = all0 ? ((const long long*)sid_raw)[b] : (long long)sw[b];
    if (s < 0) s = 0;
    if (s >= NS) s = NS - 1;
    if (t == 0) g_sid[b] = s;
    if (t < NPROMPT) g_patch[b * NPROMPT + t] = -1;

    int m = 0, pad = 0;
    if (t < L) {
        m = mask[(size_t)b * L + t];
        pad = (m == 0);
    }
    unsigned bal = __ballot_sync(0xFFFFFFFFu, pad);
    __shared__ int wtot[32];
    if (lane == 0) wtot[warp] = __popc(bal);
    __syncthreads();
    int prefix = 0;
    for (int w = 0; w < warp; ++w) prefix += wtot[w];
    int rank = prefix + __popc(bal & ((1u << lane) - 1u));

    int take = (t < L) && pad && (rank < NPROMPT);
    if (take) g_patch[b * NPROMPT + rank] = t;
    if (t < L && mask_out)
        mask_out[(size_t)b * L + t] = take ? 1.0f : (float)m;

    // flag byte per 8 rows, straight from a second ballot
    unsigned tb = __ballot_sync(0xFFFFFFFFu, take);
    if ((lane & 7) == 0 && t < L)
        g_skip8[((size_t)b * L + t) >> 3] =
            (unsigned char)((tb >> lane) & 0xFFu);
}

// ===========================================================================
// K2 mega: blocks [0, ncopy) copy RPB rows each (6 float4/thread, stores
// evict-first); blocks [ncopy, ncopy+npatch) overwrite patched rows with
// prompt data. Disjoint writes -> race-free within one kernel.
// ===========================================================================
__global__ void __launch_bounds__(256) mega_kernel(
    const float4* __restrict__ in,
    const float4* __restrict__ prompts,
    float4* __restrict__ out,
    int L, int ncopy) {
    int t = threadIdx.x;

    if ((int)blockIdx.x < ncopy) {
        // ---- COPY role ----
        int cb = blockIdx.x;
        size_t base = (size_t)cb * (RPB * DVC);   // 8*192 = 1536 = 6*256
        unsigned flags = g_skip8[cb];             // independent load

        float4 v0 = in[base + t];
        float4 v1 = in[base + t + 256];
        float4 v2 = in[base + t + 512];
        float4 v3 = in[base + t + 768];
        float4 v4 = in[base + t + 1024];
        float4 v5 = in[base + t + 1280];

        if (flags == 0) {
            __stcs(&out[base + t],        v0);
            __stcs(&out[base + t + 256],  v1);
            __stcs(&out[base + t + 512],  v2);
            __stcs(&out[base + t + 768],  v3);
            __stcs(&out[base + t + 1024], v4);
            __stcs(&out[base + t + 1280], v5);
        } else {
            if (!((flags >> ((t)        / DVC)) & 1u)) __stcs(&out[base + t],        v0);
            if (!((flags >> ((t + 256)  / DVC)) & 1u)) __stcs(&out[base + t + 256],  v1);
            if (!((flags >> ((t + 512)  / DVC)) & 1u)) __stcs(&out[base + t + 512],  v2);
            if (!((flags >> ((t + 768)  / DVC)) & 1u)) __stcs(&out[base + t + 768],  v3);
            if (!((flags >> ((t + 1024) / DVC)) & 1u)) __stcs(&out[base + t + 1024], v4);
            if (!((flags >> ((t + 1280) / DVC)) & 1u)) __stcs(&out[base + t + 1280], v5);
        }
        return;
    }

    // ---- PATCH role ----
    int slot = blockIdx.x - ncopy;               // b * NPROMPT + r
    int l = g_patch[slot];
    if (l < 0) return;
    int b = slot / NPROMPT;
    int r = slot - b * NPROMPT;
    long long s = g_sid[b];
    const float4* src = prompts + ((size_t)s * NPROMPT + r) * DVC;
    float4* dst = out + ((size_t)b * L + l) * DVC;
    if (t < DVC) dst[t] = src[t];
}

// ===========================================================================
// Fallback path (unexpected shapes): resolved-pointer prep + per-row copy.
// ===========================================================================
__global__ void prep_serial_kernel(const int* __restrict__ mask,
                                   const float* __restrict__ in,
                                   const float* __restrict__ prompts,
                                   const void* __restrict__ sid_raw,
                                   float* __restrict__ mask_out,
                                   int B, int L, int D, long long NS) {
    int b = blockIdx.x * blockDim.x + threadIdx.x;
    if (b >= B) return;
    const int* sw = (const int*)sid_raw;
    int all0 = 1;
    for (int i = 1; i < B; i += 2)
        if (sw[i] != 0) { all0 = 0; break; }
    long long s = all0 ? ((const long long*)sid_raw)[b] : (long long)sw[b];
    if (s < 0) s = 0;
    if (s >= NS) s = NS - 1;
    int cnt = 0;
    for (int l = 0; l < L; ++l) {
        size_t row = (size_t)b * L + l;
        int m = mask[row];
        int pad = (m == 0);
        int take = pad && (cnt < NPROMPT);
        const float* src = take
            ? prompts + ((size_t)s * NPROMPT + cnt) * (size_t)D
            : in + row * (size_t)D;
        g_src[row] = (unsigned long long)src;
        if (mask_out) mask_out[row] = take ? 1.0f : (float)m;
        cnt += pad;
    }
}

__global__ void copy_scalar_kernel(float* __restrict__ out, int BL, int D) {
    int row = blockIdx.x;
    if (row >= BL) return;
    const float* __restrict__ src = (const float*)g_src[row];
    float* __restrict__ dst = out + (size_t)row * D;
    for (int c = threadIdx.x; c < D; c += blockDim.x) dst[c] = src[c];
}

// ===========================================================================
extern "C" void kernel_launch(void* const* d_in, const int* in_sizes, int n_in,
                              void* d_out, int out_size) {
    // Bind inputs by size rank:
    //   smallest     -> sample_id_tensor [B]
    //   2nd smallest -> attention_mask   [B*L]
    //   2nd largest  -> input_embeds     [B*L*D]
    //   largest      -> prompt_embeddings [NS*NPROMPT*D]
    int idx[4] = {0, 1, 2, 3};
    for (int i = 0; i < 4; ++i)
        for (int j = i + 1; j < 4; ++j)
            if (in_sizes[idx[j]] < in_sizes[idx[i]]) {
                int t = idx[i]; idx[i] = idx[j]; idx[j] = t;
            }
    const void*  sid     = d_in[idx[0]];
    const int*   mask    = (const int*)d_in[idx[1]];
    const float* embeds  = (const float*)d_in[idx[2]];
    const float* prompts = (const float*)d_in[idx[3]];

    int B  = in_sizes[idx[0]];
    int BL = in_sizes[idx[1]];
    int L  = BL / B;
    long long D  = (long long)in_sizes[idx[2]] / BL;
    long long NS = (long long)in_sizes[idx[3]] / (NPROMPT * D);

    float* out = (float*)d_out;
    size_t embed_elems = (size_t)BL * (size_t)D;
    float* mask_out = ((size_t)out_size >= embed_elems + (size_t)BL)
                          ? out + embed_elems
                          : nullptr;

    bool ok = (D == 4 * DVC) && (L % RPB) == 0 && L <= 1024 &&
              B <= 4096 && BL <= (1 << 16);

    if (ok) {
        // --- K1: prep ---
        int athreads = ((L + 31) / 32) * 32;
        if (athreads < 128) athreads = 128;
        prep_kernel<<<B, athreads>>>(mask, sid, mask_out, B, L, NS);

        // --- K2: copy + patch, one node ---
        int ncopy = BL / RPB;
        int npatch = B * NPROMPT;
        mega_kernel<<<ncopy + npatch, 256>>>(
            (const float4*)embeds, (const float4*)prompts,
            (float4*)out, L, ncopy);
    } else {
        int threads = 128;
        int blocks = (B + threads - 1) / threads;
        prep_serial_kernel<<<blocks, threads>>>(mask, embeds, prompts, sid,
                                                mask_out, B, (int)L, (int)D, NS);
        int cthreads = (int)(D < 1024 ? ((D + 31) / 32) * 32 : 1024);
        copy_scalar_kernel<<<BL, cthreads>>>(out, BL, (int)D);
    }
}